// round 15
// baseline (speedup 1.0000x reference)
#include <cuda_runtime.h>
#include <cuda_fp16.h>

#define N_NODES 50000
#define N_PAD   50048               // covered by GEMM grid; row N_NODES = zero sentinel
#define N_EDGES 800000
#define F 64
#define CAP 64                      // padded CSR row capacity (max in-degree ~40)
#define GEMM_BLOCKS 782             // 64 rows per 256-thr block (2 warps per 16-row tile, n-split)
#define HIST_BLOCKS ((N_EDGES + 255) / 256)       // 3125
#define WT_STRIDE 68                // halfs; padding kills LDS bank conflicts
#define N_GROUPS ((N_NODES + 3) / 4)              // 12500 groups of 4 nodes
#define GATHER_BLOCKS 1184          // 148 SMs x 8 blocks x 256 thr = 2048 thr/SM (full occ)

// ---------------- scratch (static device globals; no allocation) -------------
__device__ __align__(16) int g_cnt_in[N_NODES];   // in-degree
__device__ __align__(16) int g_cnt_out[N_NODES];  // out-degree
__device__ int    g_eidx[N_NODES * CAP];          // padded CSR: src per slot
__device__ __align__(16) __half g_h[N_PAD * F];   // fp16 transport (pre-scaled by dout)
__device__ __align__(16) float  g_y[N_PAD * F];   // layer-1 output (fp32)

// ---------------- init --------------------------------------------------------
__global__ void k_init() {
    int i = blockIdx.x * blockDim.x + threadIdx.x;
    if (i < N_NODES / 4) {
        reinterpret_cast<int4*>(g_cnt_in)[i]  = make_int4(0, 0, 0, 0);
        reinterpret_cast<int4*>(g_cnt_out)[i] = make_int4(0, 0, 0, 0);
    }
}

// ---------------- HMMA GEMM ----------------------------------------------------
__device__ __forceinline__ unsigned f2_to_h2u(float2 v) {
    __half2 h = __floats2half2_rn(v.x, v.y);
    return *reinterpret_cast<unsigned*>(&h);
}

// Stage W (64x64 fp32 row-major) into smem TRANSPOSED fp16: Wt[n][k].
__device__ __forceinline__ void stage_wt(const float* __restrict__ W,
                                         __half* sWt, int tid, int nthreads) {
    for (int i = tid; i < F * F; i += nthreads) {
        int k = i >> 6, n = i & 63;
        sWt[n * WT_STRIDE + k] = __float2half_rn(W[i]);
    }
}

__device__ __forceinline__ void mma16816(float* c, const unsigned* a, const unsigned* b) {
    asm volatile("mma.sync.aligned.m16n8k16.row.col.f32.f16.f16.f32 "
                 "{%0,%1,%2,%3}, {%4,%5,%6,%7}, {%8,%9}, {%0,%1,%2,%3};"
                 : "+f"(c[0]), "+f"(c[1]), "+f"(c[2]), "+f"(c[3])
                 : "r"(a[0]), "r"(a[1]), "r"(a[2]), "r"(a[3]),
                   "r"(b[0]), "r"(b[1]));
}

// Warp computes D[tile_row..+16][nhalf*32 .. +32] = A @ W (n-split across 2
// warps per row-tile). Pad rows store ZERO (row N_NODES = gather sentinel).
// FOLD_DOUT scales the fp32 accumulator by deg_out^{-1/2}[row] before store.
template <bool FOLD_DOUT>
__device__ __forceinline__ void hmma_tile(int tile_row, int lane, int nhalf,
                                          const float* __restrict__ A,
                                          __half* __restrict__ Dout,
                                          const __half* sWt) {
    int g = lane >> 2;
    int t = lane & 3;
    int r0 = tile_row + g;
    int r1 = r0 + 8;
    int r0l = (r0 < N_NODES) ? r0 : 0;      // clamp loads only
    int r1l = (r1 < N_NODES) ? r1 : 0;
    const float2* A0 = reinterpret_cast<const float2*>(A + (size_t)r0l * F);
    const float2* A1 = reinterpret_cast<const float2*>(A + (size_t)r1l * F);

    float acc[4][4];
#pragma unroll
    for (int nt = 0; nt < 4; nt++)
#pragma unroll
        for (int i = 0; i < 4; i++) acc[nt][i] = 0.f;

#pragma unroll
    for (int kc = 0; kc < 4; kc++) {            // K in chunks of 16
        unsigned a[4];
        a[0] = f2_to_h2u(A0[kc * 8 + t]);
        a[1] = f2_to_h2u(A1[kc * 8 + t]);
        a[2] = f2_to_h2u(A0[kc * 8 + t + 4]);
        a[3] = f2_to_h2u(A1[kc * 8 + t + 4]);
        const __half* wk = sWt + kc * 16 + 2 * t;
#pragma unroll
        for (int nt = 0; nt < 4; nt++) {
            const __half* wr = wk + ((nhalf * 4 + nt) * 8 + g) * WT_STRIDE;
            unsigned b[2];
            b[0] = *reinterpret_cast<const unsigned*>(wr);
            b[1] = *reinterpret_cast<const unsigned*>(wr + 8);
            mma16816(acc[nt], a, b);
        }
    }

    float d0 = 1.f, d1 = 1.f;
    if (FOLD_DOUT) {
        int c0 = (r0 < N_NODES) ? g_cnt_out[r0] : 0;
        int c1 = (r1 < N_NODES) ? g_cnt_out[r1] : 0;
        d0 = (c0 > 0) ? rsqrtf((float)c0) : 0.f;
        d1 = (c1 > 0) ? rsqrtf((float)c1) : 0.f;
    }
    bool v0 = (r0 < N_NODES), v1 = (r1 < N_NODES);
    __half2 z = __floats2half2_rn(0.f, 0.f);
#pragma unroll
    for (int nt = 0; nt < 4; nt++) {
        int col = (nhalf * 4 + nt) * 8 + 2 * t;
        __half2 o0 = v0 ? __floats2half2_rn(acc[nt][0] * d0, acc[nt][1] * d0) : z;
        __half2 o1 = v1 ? __floats2half2_rn(acc[nt][2] * d1, acc[nt][3] * d1) : z;
        *reinterpret_cast<__half2*>(Dout + (size_t)r0 * F + col) = o0;
        *reinterpret_cast<__half2*>(Dout + (size_t)r1 * F + col) = o1;
    }
}

// ---------------- fused: HMMA GEMM-1 (blocks [0,782)) + hist/bin (rest) ------
// GEMM-1 cannot fold dout (hist runs concurrently) -> k_scale applies it after.
__global__ void __launch_bounds__(256) k_fused(const float* __restrict__ x,
                                               const float* __restrict__ W1,
                                               const int* __restrict__ src,
                                               const int* __restrict__ dst) {
    __shared__ __align__(16) __half sWt[F * WT_STRIDE];
    if (blockIdx.x < GEMM_BLOCKS) {
        stage_wt(W1, sWt, threadIdx.x, 256);
        __syncthreads();
        int warp = threadIdx.x >> 5;
        hmma_tile<false>(blockIdx.x * 64 + (warp >> 1) * 16, threadIdx.x & 31,
                         warp & 1, x, g_h, sWt);
    } else {
        int e = (blockIdx.x - GEMM_BLOCKS) * 256 + threadIdx.x;
        if (e < N_EDGES) {
            int d = dst[e];
            int s = src[e];
            int pos = atomicAdd(&g_cnt_in[d], 1);
            if (pos < CAP) g_eidx[d * CAP + pos] = s;   // single-pass bin
            atomicAdd(&g_cnt_out[s], 1);                // no return -> RED
        }
    }
}

// ---------------- scale layer-1 h rows by dout (in place, fp16) --------------
// One uint4 = 16 bytes = 8 halfs per thread; 8 uint4 per 64-half row.
__global__ void __launch_bounds__(256) k_scale() {
    int i = blockIdx.x * blockDim.x + threadIdx.x;
    if (i >= N_NODES * 8) return;
    int row = i >> 3;
    int c = g_cnt_out[row];
    float d = (c > 0) ? rsqrtf((float)c) : 0.f;
    uint4 v = reinterpret_cast<uint4*>(g_h)[i];
    __half2* p = reinterpret_cast<__half2*>(&v);
#pragma unroll
    for (int q = 0; q < 4; q++) {
        float2 f = __half22float2(p[q]);
        p[q] = __floats2half2_rn(f.x * d, f.y * d);
    }
    reinterpret_cast<uint4*>(g_h)[i] = v;
}

// ---------------- standalone HMMA GEMM (layer 2): folds dout ------------------
__global__ void __launch_bounds__(256) k_gemm(const float* __restrict__ y,
                                              const float* __restrict__ W,
                                              __half* __restrict__ hout) {
    __shared__ __align__(16) __half sWt[F * WT_STRIDE];
    stage_wt(W, sWt, threadIdx.x, 256);
    __syncthreads();
    int warp = threadIdx.x >> 5;
    hmma_tile<true>(blockIdx.x * 64 + (warp >> 1) * 16, threadIdx.x & 31,
                    warp & 1, y, hout, sWt);
}

// ---------------- full-occupancy 4-node pull-gather ---------------------------
// 1184 blocks = 8 resident blocks/SM = 2048 threads/SM: doubles resident warps
// and outstanding L2 loads vs the 592-block run (the measured limiter was
// latency x MLP at occ=40%). Grid-stride over 12500 groups of 4 nodes.
// h pre-scaled by dout: per slot SHFL + LDG + cvt + 2 FADD. Slots past a
// node's degree point at sentinel row N_NODES (zeros, L1-hot).
template <bool RELU>
__global__ void __launch_bounds__(256) k_gather4p(const __half* __restrict__ h,
                                                  const float* __restrict__ b,
                                                  float* __restrict__ out) {
    int lane = threadIdx.x & 31;
    int warp0 = (blockIdx.x * blockDim.x + threadIdx.x) >> 5;
    int nwarps = (GATHER_BLOCKS * 256) >> 5;
    float2 bb = *reinterpret_cast<const float2*>(b + lane * 2);

    for (int grp = warp0; grp < N_GROUPS; grp += nwarps) {
        int w0 = grp * 4;

        int cntv[4], sA[4];
        int maxn = 0;
#pragma unroll
        for (int i = 0; i < 4; i++) {
            int cnt = g_cnt_in[w0 + i];           // w0+3 <= 49999 (50000 = 4*12500)
            cntv[i] = cnt;
            int n = (cnt < CAP) ? cnt : CAP;
            maxn = (n > maxn) ? n : maxn;
            sA[i] = (lane < n) ? g_eidx[(w0 + i) * CAP + lane] : N_NODES;
        }

        float2 acc[4];
#pragma unroll
        for (int i = 0; i < 4; i++) acc[i] = make_float2(0.f, 0.f);

        int jmax = (maxn < 32) ? maxn : 32;
#pragma unroll 2
        for (int j = 0; j < jmax; j++) {
#pragma unroll
            for (int i = 0; i < 4; i++) {
                int s = __shfl_sync(0xffffffffu, sA[i], j);
                __half2 hv = *reinterpret_cast<const __half2*>(h + (size_t)s * F + lane * 2);
                float2 v = __half22float2(hv);
                acc[i].x += v.x;
                acc[i].y += v.y;
            }
        }

        if (maxn > 32) {                          // rare: any of the 4 has deg > 32
            int sB[4];
#pragma unroll
            for (int i = 0; i < 4; i++) {
                int n = (cntv[i] < CAP) ? cntv[i] : CAP;
                sB[i] = (lane + 32 < n) ? g_eidx[(w0 + i) * CAP + lane + 32] : N_NODES;
            }
            int m = maxn - 32;
            for (int j = 0; j < m; j++) {
#pragma unroll
                for (int i = 0; i < 4; i++) {
                    int s = __shfl_sync(0xffffffffu, sB[i], j);
                    __half2 hv = *reinterpret_cast<const __half2*>(h + (size_t)s * F + lane * 2);
                    float2 v = __half22float2(hv);
                    acc[i].x += v.x;
                    acc[i].y += v.y;
                }
            }
        }

#pragma unroll
        for (int i = 0; i < 4; i++) {
            float din = (cntv[i] > 0) ? rsqrtf((float)cntv[i]) : 0.f;
            float2 r;
            r.x = fmaf(acc[i].x, din, bb.x);
            r.y = fmaf(acc[i].y, din, bb.y);
            if (RELU) {
                r.x = fmaxf(r.x, 0.f);
                r.y = fmaxf(r.y, 0.f);
            }
            *reinterpret_cast<float2*>(out + (size_t)(w0 + i) * F + lane * 2) = r;
        }
    }
}

// ---------------- launch -----------------------------------------------------
extern "C" void kernel_launch(void* const* d_in, const int* in_sizes, int n_in,
                              void* d_out, int out_size) {
    const float* x  = (const float*)d_in[0];
    const float* W1 = (const float*)d_in[1];
    const float* b1 = (const float*)d_in[2];
    const float* W2 = (const float*)d_in[3];
    const float* b2 = (const float*)d_in[4];
    const int* src  = (const int*)d_in[5];
    const int* dst  = (const int*)d_in[6];
    float* out = (float*)d_out;

    __half* p_h;
    float* p_y;
    cudaGetSymbolAddress((void**)&p_h, g_h);
    cudaGetSymbolAddress((void**)&p_y, g_y);

    const int T = 256;
    auto cdiv = [](int a, int b) { return (a + b - 1) / b; };

    k_init<<<cdiv(N_NODES / 4, T), T>>>();
    k_fused<<<GEMM_BLOCKS + HIST_BLOCKS, 256>>>(x, W1, src, dst);
    k_scale<<<cdiv(N_NODES * 8, T), T>>>();

    k_gather4p<true><<<GATHER_BLOCKS, T>>>(p_h, b1, p_y);
    k_gemm<<<GEMM_BLOCKS, 256>>>(p_y, W2, p_h);
    k_gather4p<false><<<GATHER_BLOCKS, T>>>(p_h, b2, out);
}

// round 16
// speedup vs baseline: 1.0654x; 1.0654x over previous
#include <cuda_runtime.h>
#include <cuda_fp16.h>

#define N_NODES 50000
#define N_PAD   50048               // covered by GEMM grid; row N_NODES = zero sentinel
#define N_EDGES 800000
#define F 64
#define CAP 64                      // padded CSR row capacity (max in-degree ~40)
#define GEMM_BLOCKS 782             // 64 rows per 256-thr block (2 warps per 16-row tile, n-split)
#define HIST_BLOCKS ((N_EDGES + 255) / 256)       // 3125
#define WT_STRIDE 68                // halfs; padding kills LDS bank conflicts
#define N_GROUPS ((N_NODES + 3) / 4)              // 12500 groups of 4 nodes
#define GATHER_BLOCKS 592           // 148 x 4 blocks (R15 showed higher occ hurts)

// ---------------- scratch (static device globals; no allocation) -------------
__device__ __align__(16) int g_cnt_in[N_NODES];   // in-degree
__device__ __align__(16) int g_cnt_out[N_NODES];  // out-degree
__device__ int    g_eidx[N_NODES * CAP];          // padded CSR: src per slot
__device__ __align__(16) __half g_h[N_PAD * F];   // fp16 transport (pre-scaled by dout)
__device__ __align__(16) float  g_y[N_PAD * F];   // layer-1 output (fp32)

// ---------------- init --------------------------------------------------------
__global__ void k_init() {
    int i = blockIdx.x * blockDim.x + threadIdx.x;
    if (i < N_NODES / 4) {
        reinterpret_cast<int4*>(g_cnt_in)[i]  = make_int4(0, 0, 0, 0);
        reinterpret_cast<int4*>(g_cnt_out)[i] = make_int4(0, 0, 0, 0);
    }
}

// ---------------- HMMA GEMM ----------------------------------------------------
__device__ __forceinline__ unsigned f2_to_h2u(float2 v) {
    __half2 h = __floats2half2_rn(v.x, v.y);
    return *reinterpret_cast<unsigned*>(&h);
}

// Stage W (64x64 fp32 row-major) into smem TRANSPOSED fp16: Wt[n][k].
__device__ __forceinline__ void stage_wt(const float* __restrict__ W,
                                         __half* sWt, int tid, int nthreads) {
    for (int i = tid; i < F * F; i += nthreads) {
        int k = i >> 6, n = i & 63;
        sWt[n * WT_STRIDE + k] = __float2half_rn(W[i]);
    }
}

__device__ __forceinline__ void mma16816(float* c, const unsigned* a, const unsigned* b) {
    asm volatile("mma.sync.aligned.m16n8k16.row.col.f32.f16.f16.f32 "
                 "{%0,%1,%2,%3}, {%4,%5,%6,%7}, {%8,%9}, {%0,%1,%2,%3};"
                 : "+f"(c[0]), "+f"(c[1]), "+f"(c[2]), "+f"(c[3])
                 : "r"(a[0]), "r"(a[1]), "r"(a[2]), "r"(a[3]),
                   "r"(b[0]), "r"(b[1]));
}

// Warp computes D[tile_row..+16][nhalf*32 .. +32] = A @ W (n-split across 2
// warps per row-tile). Pad rows store ZERO (row N_NODES = gather sentinel).
// FOLD_DOUT scales the fp32 accumulator by deg_out^{-1/2}[row] before store.
template <bool FOLD_DOUT>
__device__ __forceinline__ void hmma_tile(int tile_row, int lane, int nhalf,
                                          const float* __restrict__ A,
                                          __half* __restrict__ Dout,
                                          const __half* sWt) {
    int g = lane >> 2;
    int t = lane & 3;
    int r0 = tile_row + g;
    int r1 = r0 + 8;
    int r0l = (r0 < N_NODES) ? r0 : 0;      // clamp loads only
    int r1l = (r1 < N_NODES) ? r1 : 0;
    const float2* A0 = reinterpret_cast<const float2*>(A + (size_t)r0l * F);
    const float2* A1 = reinterpret_cast<const float2*>(A + (size_t)r1l * F);

    float acc[4][4];
#pragma unroll
    for (int nt = 0; nt < 4; nt++)
#pragma unroll
        for (int i = 0; i < 4; i++) acc[nt][i] = 0.f;

#pragma unroll
    for (int kc = 0; kc < 4; kc++) {            // K in chunks of 16
        unsigned a[4];
        a[0] = f2_to_h2u(A0[kc * 8 + t]);
        a[1] = f2_to_h2u(A1[kc * 8 + t]);
        a[2] = f2_to_h2u(A0[kc * 8 + t + 4]);
        a[3] = f2_to_h2u(A1[kc * 8 + t + 4]);
        const __half* wk = sWt + kc * 16 + 2 * t;
#pragma unroll
        for (int nt = 0; nt < 4; nt++) {
            const __half* wr = wk + ((nhalf * 4 + nt) * 8 + g) * WT_STRIDE;
            unsigned b[2];
            b[0] = *reinterpret_cast<const unsigned*>(wr);
            b[1] = *reinterpret_cast<const unsigned*>(wr + 8);
            mma16816(acc[nt], a, b);
        }
    }

    float d0 = 1.f, d1 = 1.f;
    if (FOLD_DOUT) {
        int c0 = (r0 < N_NODES) ? g_cnt_out[r0] : 0;
        int c1 = (r1 < N_NODES) ? g_cnt_out[r1] : 0;
        d0 = (c0 > 0) ? rsqrtf((float)c0) : 0.f;
        d1 = (c1 > 0) ? rsqrtf((float)c1) : 0.f;
    }
    bool v0 = (r0 < N_NODES), v1 = (r1 < N_NODES);
    __half2 z = __floats2half2_rn(0.f, 0.f);
#pragma unroll
    for (int nt = 0; nt < 4; nt++) {
        int col = (nhalf * 4 + nt) * 8 + 2 * t;
        __half2 o0 = v0 ? __floats2half2_rn(acc[nt][0] * d0, acc[nt][1] * d0) : z;
        __half2 o1 = v1 ? __floats2half2_rn(acc[nt][2] * d1, acc[nt][3] * d1) : z;
        *reinterpret_cast<__half2*>(Dout + (size_t)r0 * F + col) = o0;
        *reinterpret_cast<__half2*>(Dout + (size_t)r1 * F + col) = o1;
    }
}

// ---------------- fused: HMMA GEMM-1 (blocks [0,782)) + hist/bin (rest) ------
// GEMM-1 cannot fold dout (hist runs concurrently) -> k_scale applies it after.
__global__ void __launch_bounds__(256) k_fused(const float* __restrict__ x,
                                               const float* __restrict__ W1,
                                               const int* __restrict__ src,
                                               const int* __restrict__ dst) {
    __shared__ __align__(16) __half sWt[F * WT_STRIDE];
    if (blockIdx.x < GEMM_BLOCKS) {
        stage_wt(W1, sWt, threadIdx.x, 256);
        __syncthreads();
        int warp = threadIdx.x >> 5;
        hmma_tile<false>(blockIdx.x * 64 + (warp >> 1) * 16, threadIdx.x & 31,
                         warp & 1, x, g_h, sWt);
    } else {
        int e = (blockIdx.x - GEMM_BLOCKS) * 256 + threadIdx.x;
        if (e < N_EDGES) {
            int d = dst[e];
            int s = src[e];
            int pos = atomicAdd(&g_cnt_in[d], 1);
            if (pos < CAP) g_eidx[d * CAP + pos] = s;   // single-pass bin
            atomicAdd(&g_cnt_out[s], 1);                // no return -> RED
        }
    }
}

// ---------------- scale layer-1 h rows by dout (in place, fp16) --------------
// One uint4 = 16 bytes = 8 halfs per thread; 8 uint4 per 64-half row.
__global__ void __launch_bounds__(256) k_scale() {
    int i = blockIdx.x * blockDim.x + threadIdx.x;
    if (i >= N_NODES * 8) return;
    int row = i >> 3;
    int c = g_cnt_out[row];
    float d = (c > 0) ? rsqrtf((float)c) : 0.f;
    uint4 v = reinterpret_cast<uint4*>(g_h)[i];
    __half2* p = reinterpret_cast<__half2*>(&v);
#pragma unroll
    for (int q = 0; q < 4; q++) {
        float2 f = __half22float2(p[q]);
        p[q] = __floats2half2_rn(f.x * d, f.y * d);
    }
    reinterpret_cast<uint4*>(g_h)[i] = v;
}

// ---------------- standalone HMMA GEMM (layer 2): folds dout ------------------
__global__ void __launch_bounds__(256) k_gemm(const float* __restrict__ y,
                                              const float* __restrict__ W,
                                              __half* __restrict__ hout) {
    __shared__ __align__(16) __half sWt[F * WT_STRIDE];
    stage_wt(W, sWt, threadIdx.x, 256);
    __syncthreads();
    int warp = threadIdx.x >> 5;
    hmma_tile<true>(blockIdx.x * 64 + (warp >> 1) * 16, threadIdx.x & 31,
                    warp & 1, y, hout, sWt);
}

// ---------------- quad pull-gather --------------------------------------------
// The measured limiter was LSU/MIO issue (1 LDG.32 + 1 SHFL per edge). Here a
// QUAD of 8 lanes owns one node (16B/lane x 8 = the full 128B row), so ONE
// LDG.128 warp-instruction fetches 4 edge rows, and the slot index comes from
// a per-quad broadcast LDG.32 that is L1-hot (256B of eidx per node reused
// across ~20 steps) — no SHFLs at all. LSU ops/edge: 2.0 -> ~0.55.
// h is pre-scaled by dout; slots past a node's degree use sentinel row N_NODES.
template <bool RELU>
__global__ void __launch_bounds__(256) k_gatherq(const __half* __restrict__ h,
                                                 const float* __restrict__ b,
                                                 float* __restrict__ out) {
    int lane = threadIdx.x & 31;
    int q   = lane >> 3;        // which of the 4 nodes this lane serves
    int sub = lane & 7;         // owns cols [sub*8, sub*8+8)
    int warp0 = (blockIdx.x * blockDim.x + threadIdx.x) >> 5;
    int nwarps = (GATHER_BLOCKS * 256) >> 5;

    float bb[8];                // bias for owned cols (loop-invariant)
#pragma unroll
    for (int c = 0; c < 8; c++) bb[c] = __ldg(b + sub * 8 + c);

    for (int grp = warp0; grp < N_GROUPS; grp += nwarps) {
        int w = grp * 4 + q;                    // this quad's node (< 50000)
        int cnt = g_cnt_in[w];                  // 8 lanes same addr: broadcast
        int n = (cnt < CAP) ? cnt : CAP;
        int jmax = __reduce_max_sync(0xffffffffu, n);
        const int* eptr = g_eidx + w * CAP;

        float acc[8];
#pragma unroll
        for (int c = 0; c < 8; c++) acc[c] = 0.f;

#pragma unroll 2
        for (int j = 0; j < jmax; j++) {
            int s = (j < n) ? __ldg(eptr + j) : N_NODES;   // L1-hot index
            uint4 hv = *reinterpret_cast<const uint4*>(h + (size_t)s * F + sub * 8);
            const __half2* p = reinterpret_cast<const __half2*>(&hv);
#pragma unroll
            for (int t = 0; t < 4; t++) {
                float2 v = __half22float2(p[t]);
                acc[2 * t]     += v.x;
                acc[2 * t + 1] += v.y;
            }
        }

        float din = (cnt > 0) ? rsqrtf((float)cnt) : 0.f;
        float4 r0, r1;
        r0.x = fmaf(acc[0], din, bb[0]);
        r0.y = fmaf(acc[1], din, bb[1]);
        r0.z = fmaf(acc[2], din, bb[2]);
        r0.w = fmaf(acc[3], din, bb[3]);
        r1.x = fmaf(acc[4], din, bb[4]);
        r1.y = fmaf(acc[5], din, bb[5]);
        r1.z = fmaf(acc[6], din, bb[6]);
        r1.w = fmaf(acc[7], din, bb[7]);
        if (RELU) {
            r0.x = fmaxf(r0.x, 0.f); r0.y = fmaxf(r0.y, 0.f);
            r0.z = fmaxf(r0.z, 0.f); r0.w = fmaxf(r0.w, 0.f);
            r1.x = fmaxf(r1.x, 0.f); r1.y = fmaxf(r1.y, 0.f);
            r1.z = fmaxf(r1.z, 0.f); r1.w = fmaxf(r1.w, 0.f);
        }
        float* op = out + (size_t)w * F + sub * 8;
        *reinterpret_cast<float4*>(op)     = r0;
        *reinterpret_cast<float4*>(op + 4) = r1;
    }
}

// ---------------- launch -----------------------------------------------------
extern "C" void kernel_launch(void* const* d_in, const int* in_sizes, int n_in,
                              void* d_out, int out_size) {
    const float* x  = (const float*)d_in[0];
    const float* W1 = (const float*)d_in[1];
    const float* b1 = (const float*)d_in[2];
    const float* W2 = (const float*)d_in[3];
    const float* b2 = (const float*)d_in[4];
    const int* src  = (const int*)d_in[5];
    const int* dst  = (const int*)d_in[6];
    float* out = (float*)d_out;

    __half* p_h;
    float* p_y;
    cudaGetSymbolAddress((void**)&p_h, g_h);
    cudaGetSymbolAddress((void**)&p_y, g_y);

    const int T = 256;
    auto cdiv = [](int a, int b) { return (a + b - 1) / b; };

    k_init<<<cdiv(N_NODES / 4, T), T>>>();
    k_fused<<<GEMM_BLOCKS + HIST_BLOCKS, 256>>>(x, W1, src, dst);
    k_scale<<<cdiv(N_NODES * 8, T), T>>>();

    k_gatherq<true><<<GATHER_BLOCKS, T>>>(p_h, b1, p_y);
    k_gemm<<<GEMM_BLOCKS, 256>>>(p_y, W2, p_h);
    k_gatherq<false><<<GATHER_BLOCKS, T>>>(p_h, b2, out);
}

// round 17
// speedup vs baseline: 1.1473x; 1.0769x over previous
#include <cuda_runtime.h>
#include <cuda_fp16.h>

#define N_NODES 50000
#define N_PAD   50048               // GEMM grid covers pad rows (stores clamped rows' results there)
#define N_EDGES 800000
#define F 64
#define CAP 64                      // padded CSR row capacity (max in-degree ~40)
#define GEMM_BLOCKS 782             // 64 rows per 256-thr block (2 warps per 16-row tile, n-split)
#define HIST_BLOCKS ((N_EDGES + 255) / 256)       // 3125
#define WT_STRIDE 68                // halfs; padding kills LDS bank conflicts
// Gather: 4 nodes per warp, non-persistent (R11 geometry — best measured).
#define GATHER_WARPS ((N_NODES + 3) / 4)
#define GATHER_BLOCKS ((GATHER_WARPS * 32 + 255) / 256)

// ---------------- scratch (static device globals; no allocation) -------------
__device__ __align__(16) int g_cnt_in[N_NODES];   // in-degree
__device__ __align__(16) int g_cnt_out[N_NODES];  // out-degree
__device__ int    g_eidx[N_NODES * CAP];          // padded CSR: src per slot
__device__ __align__(16) __half g_h[N_PAD * F];   // fp16 transport features
__device__ __align__(16) float  g_y[N_PAD * F];   // layer-1 output (fp32)

// ---------------- init --------------------------------------------------------
__global__ void k_init() {
    int i = blockIdx.x * blockDim.x + threadIdx.x;
    if (i < N_NODES / 4) {
        reinterpret_cast<int4*>(g_cnt_in)[i]  = make_int4(0, 0, 0, 0);
        reinterpret_cast<int4*>(g_cnt_out)[i] = make_int4(0, 0, 0, 0);
    }
}

// ---------------- HMMA GEMM ----------------------------------------------------
__device__ __forceinline__ unsigned f2_to_h2u(float2 v) {
    __half2 h = __floats2half2_rn(v.x, v.y);
    return *reinterpret_cast<unsigned*>(&h);
}

// Stage W (64x64 fp32 row-major) into smem TRANSPOSED fp16: Wt[n][k].
__device__ __forceinline__ void stage_wt(const float* __restrict__ W,
                                         __half* sWt, int tid, int nthreads) {
    for (int i = tid; i < F * F; i += nthreads) {
        int k = i >> 6, n = i & 63;
        sWt[n * WT_STRIDE + k] = __float2half_rn(W[i]);
    }
}

__device__ __forceinline__ void mma16816(float* c, const unsigned* a, const unsigned* b) {
    asm volatile("mma.sync.aligned.m16n8k16.row.col.f32.f16.f16.f32 "
                 "{%0,%1,%2,%3}, {%4,%5,%6,%7}, {%8,%9}, {%0,%1,%2,%3};"
                 : "+f"(c[0]), "+f"(c[1]), "+f"(c[2]), "+f"(c[3])
                 : "r"(a[0]), "r"(a[1]), "r"(a[2]), "r"(a[3]),
                   "r"(b[0]), "r"(b[1]));
}

// n-split HMMA tile: warp computes D[tile_row..+16][nhalf*32 .. +32] = A @ W.
// 2 warps per 16-row tile (halved per-warp latency chain vs full-width; the
// A-row LDGs are shared via L1). Rows >= N_NODES are load-clamped; their
// results land in pad rows (never read).
__device__ __forceinline__ void hmma_tile(int tile_row, int lane, int nhalf,
                                          const float* __restrict__ A,
                                          __half* __restrict__ Dout,
                                          const __half* sWt) {
    int g = lane >> 2;
    int t = lane & 3;
    int r0 = tile_row + g;
    int r1 = r0 + 8;
    int r0l = (r0 < N_NODES) ? r0 : 0;      // clamp loads only
    int r1l = (r1 < N_NODES) ? r1 : 0;
    const float2* A0 = reinterpret_cast<const float2*>(A + (size_t)r0l * F);
    const float2* A1 = reinterpret_cast<const float2*>(A + (size_t)r1l * F);

    float acc[4][4];
#pragma unroll
    for (int nt = 0; nt < 4; nt++)
#pragma unroll
        for (int i = 0; i < 4; i++) acc[nt][i] = 0.f;

#pragma unroll
    for (int kc = 0; kc < 4; kc++) {            // K in chunks of 16
        unsigned a[4];
        a[0] = f2_to_h2u(A0[kc * 8 + t]);
        a[1] = f2_to_h2u(A1[kc * 8 + t]);
        a[2] = f2_to_h2u(A0[kc * 8 + t + 4]);
        a[3] = f2_to_h2u(A1[kc * 8 + t + 4]);
        const __half* wk = sWt + kc * 16 + 2 * t;
#pragma unroll
        for (int nt = 0; nt < 4; nt++) {
            const __half* wr = wk + ((nhalf * 4 + nt) * 8 + g) * WT_STRIDE;
            unsigned b[2];
            b[0] = *reinterpret_cast<const unsigned*>(wr);
            b[1] = *reinterpret_cast<const unsigned*>(wr + 8);
            mma16816(acc[nt], a, b);
        }
    }

#pragma unroll
    for (int nt = 0; nt < 4; nt++) {
        int col = (nhalf * 4 + nt) * 8 + 2 * t;
        __half2 o0 = __floats2half2_rn(acc[nt][0], acc[nt][1]);
        __half2 o1 = __floats2half2_rn(acc[nt][2], acc[nt][3]);
        *reinterpret_cast<__half2*>(Dout + (size_t)r0 * F + col) = o0;
        *reinterpret_cast<__half2*>(Dout + (size_t)r1 * F + col) = o1;
    }
}

// ---------------- fused: HMMA GEMM-1 (blocks [0,782)) + hist/bin (rest) ------
__global__ void __launch_bounds__(256) k_fused(const float* __restrict__ x,
                                               const float* __restrict__ W1,
                                               const int* __restrict__ src,
                                               const int* __restrict__ dst) {
    __shared__ __align__(16) __half sWt[F * WT_STRIDE];
    if (blockIdx.x < GEMM_BLOCKS) {
        stage_wt(W1, sWt, threadIdx.x, 256);
        __syncthreads();
        int warp = threadIdx.x >> 5;
        hmma_tile(blockIdx.x * 64 + (warp >> 1) * 16, threadIdx.x & 31,
                  warp & 1, x, g_h, sWt);
    } else {
        int e = (blockIdx.x - GEMM_BLOCKS) * 256 + threadIdx.x;
        if (e < N_EDGES) {
            int d = dst[e];
            int s = src[e];
            int pos = atomicAdd(&g_cnt_in[d], 1);
            if (pos < CAP) g_eidx[d * CAP + pos] = s;   // single-pass bin
            atomicAdd(&g_cnt_out[s], 1);                // no return -> RED
        }
    }
}

// ---------------- standalone HMMA GEMM (layer 2): fp32 y -> fp16 h -----------
__global__ void __launch_bounds__(256) k_gemm(const float* __restrict__ y,
                                              const float* __restrict__ W,
                                              __half* __restrict__ hout) {
    __shared__ __align__(16) __half sWt[F * WT_STRIDE];
    stage_wt(W, sWt, threadIdx.x, 256);
    __syncthreads();
    int warp = threadIdx.x >> 5;
    hmma_tile(blockIdx.x * 64 + (warp >> 1) * 16, threadIdx.x & 31,
              warp & 1, y, hout, sWt);
}

// ---------------- 4-node interleaved pull-gather (R11 verbatim) --------------
// Warp processes 4 nodes concurrently: 4 independent SHFL->LDG->FMA chains per
// loop step. Lanes >= n_i carry s=0/d=0, so steps past a node's degree
// self-mask (row 0 stays L1-hot, d=0).
template <bool RELU>
__global__ void __launch_bounds__(256) k_gather4(const __half* __restrict__ h,
                                                 const float* __restrict__ b,
                                                 float* __restrict__ out) {
    int warp = (blockIdx.x * blockDim.x + threadIdx.x) >> 5;
    int w0 = warp * 4;
    if (w0 >= N_NODES) return;
    int lane = threadIdx.x & 31;

    int cntv[4], sA[4];
    float dA[4];
    int maxn = 0;
#pragma unroll
    for (int i = 0; i < 4; i++) {
        int w = w0 + i;
        int cnt = (w < N_NODES) ? g_cnt_in[w] : 0;
        cntv[i] = cnt;
        int n = (cnt < CAP) ? cnt : CAP;
        maxn = (n > maxn) ? n : maxn;
        sA[i] = 0; dA[i] = 0.f;
        if (w < N_NODES && lane < n) {
            sA[i] = g_eidx[w * CAP + lane];              // coalesced 128B
            dA[i] = rsqrtf((float)g_cnt_out[sA[i]]);
        }
    }

    float2 acc[4];
#pragma unroll
    for (int i = 0; i < 4; i++) acc[i] = make_float2(0.f, 0.f);

    int jmax = (maxn < 32) ? maxn : 32;
    for (int j = 0; j < jmax; j++) {
#pragma unroll
        for (int i = 0; i < 4; i++) {
            int s   = __shfl_sync(0xffffffffu, sA[i], j);
            float d = __shfl_sync(0xffffffffu, dA[i], j);
            __half2 hv = *reinterpret_cast<const __half2*>(h + (size_t)s * F + lane * 2);
            float2 v = __half22float2(hv);
            acc[i].x = fmaf(v.x, d, acc[i].x);
            acc[i].y = fmaf(v.y, d, acc[i].y);
        }
    }

    if (maxn > 32) {                          // rare: any of the 4 has deg > 32
        int sB[4]; float dB[4];
#pragma unroll
        for (int i = 0; i < 4; i++) {
            sB[i] = 0; dB[i] = 0.f;
            int w = w0 + i;
            int n = (cntv[i] < CAP) ? cntv[i] : CAP;
            if (w < N_NODES && lane + 32 < n) {
                sB[i] = g_eidx[w * CAP + lane + 32];
                dB[i] = rsqrtf((float)g_cnt_out[sB[i]]);
            }
        }
        int m = maxn - 32;
        for (int j = 0; j < m; j++) {
#pragma unroll
            for (int i = 0; i < 4; i++) {
                int s   = __shfl_sync(0xffffffffu, sB[i], j);
                float d = __shfl_sync(0xffffffffu, dB[i], j);
                __half2 hv = *reinterpret_cast<const __half2*>(h + (size_t)s * F + lane * 2);
                float2 v = __half22float2(hv);
                acc[i].x = fmaf(v.x, d, acc[i].x);
                acc[i].y = fmaf(v.y, d, acc[i].y);
            }
        }
    }

    float2 bb = *reinterpret_cast<const float2*>(b + lane * 2);
#pragma unroll
    for (int i = 0; i < 4; i++) {
        int w = w0 + i;
        if (w >= N_NODES) break;
        float din = (cntv[i] > 0) ? rsqrtf((float)cntv[i]) : 0.f;
        float2 r;
        r.x = fmaf(acc[i].x, din, bb.x);
        r.y = fmaf(acc[i].y, din, bb.y);
        if (RELU) {
            r.x = fmaxf(r.x, 0.f);
            r.y = fmaxf(r.y, 0.f);
        }
        *reinterpret_cast<float2*>(out + (size_t)w * F + lane * 2) = r;
    }
}

// ---------------- launch -----------------------------------------------------
extern "C" void kernel_launch(void* const* d_in, const int* in_sizes, int n_in,
                              void* d_out, int out_size) {
    const float* x  = (const float*)d_in[0];
    const float* W1 = (const float*)d_in[1];
    const float* b1 = (const float*)d_in[2];
    const float* W2 = (const float*)d_in[3];
    const float* b2 = (const float*)d_in[4];
    const int* src  = (const int*)d_in[5];
    const int* dst  = (const int*)d_in[6];
    float* out = (float*)d_out;

    __half* p_h;
    float* p_y;
    cudaGetSymbolAddress((void**)&p_h, g_h);
    cudaGetSymbolAddress((void**)&p_y, g_y);

    const int T = 256;
    auto cdiv = [](int a, int b) { return (a + b - 1) / b; };

    k_init<<<cdiv(N_NODES / 4, T), T>>>();
    k_fused<<<GEMM_BLOCKS + HIST_BLOCKS, 256>>>(x, W1, src, dst);

    k_gather4<true><<<GATHER_BLOCKS, T>>>(p_h, b1, p_y);
    k_gemm<<<GEMM_BLOCKS, 256>>>(p_y, W2, p_h);
    k_gather4<false><<<GATHER_BLOCKS, T>>>(p_h, b2, out);
}